// round 1
// baseline (speedup 1.0000x reference)
#include <cuda_runtime.h>
#include <cuda_bf16.h>

// Problem constants
#define B_  8192
#define M_  50000
#define NU_ 16
#define F_  128
#define E_  65536

// Scratch (device globals — no allocation allowed)
__device__ float4 g_feats4[B_ * (F_ / 4)];   // mo + h1_agg   [B,F]
__device__ float4 g_h2agg4[B_ * (F_ / 4)];   // h2_agg        [B,F]
__device__ int    g_winner[M_];              // per-V_n-row winning b (max b), -1 if untouched

// ---------------------------------------------------------------------------
// Kernel 1: init scratch (runs every launch — graph replays must be deterministic)
// ---------------------------------------------------------------------------
__global__ void init_kernel(const float4* __restrict__ mo4) {
    int t = blockIdx.x * blockDim.x + threadIdx.x;
    const int NV = B_ * (F_ / 4);  // 262144
    if (t < NV) {
        g_feats4[t] = mo4[t];
        g_h2agg4[t] = make_float4(0.f, 0.f, 0.f, 0.f);
    }
    if (t < M_) g_winner[t] = -1;
}

// ---------------------------------------------------------------------------
// Kernel 2: segment sums via float4 atomics + winner resolution
//   thread t: e = t/32, c = t%32 (one float4 chunk of a 128-float row)
// ---------------------------------------------------------------------------
__global__ void scatter_kernel(const float4* __restrict__ h1_4,
                               const int*    __restrict__ h1_idx,
                               const float4* __restrict__ h2_4,
                               const int*    __restrict__ h2_idx,
                               const int*    __restrict__ v_idx) {
    int t = blockIdx.x * blockDim.x + threadIdx.x;
    if (t < E_ * 32) {
        int e = t >> 5;
        int c = t & 31;
        float4 a = h1_4[t];
        atomicAdd(&g_feats4[h1_idx[e] * 32 + c], a);
        float4 b = h2_4[t];
        atomicAdd(&g_h2agg4[h2_idx[e] * 32 + c], b);
    }
    if (t < B_) {
        // last-update-wins (CPU XLA scatter order) == max b wins
        atomicMax(&g_winner[v_idx[t]], t);
    }
}

// ---------------------------------------------------------------------------
// Kernel 3: per-b energy + winner top_states write
//   1 block per b, 512 threads = 16 warps; warp u owns candidate state u.
// ---------------------------------------------------------------------------
__global__ __launch_bounds__(512)
void energy_kernel(const float*  __restrict__ mo,
                   const float*  __restrict__ Vn,
                   const int*    __restrict__ v_idx,
                   const float*  __restrict__ gram,
                   float*        __restrict__ energy_out,
                   float*        __restrict__ vout) {
    int b    = blockIdx.x;
    int lane = threadIdx.x & 31;
    int u    = threadIdx.x >> 5;   // 0..15

    __shared__ float4 mo_s[32];    // mo_features[b,:]
    __shared__ float4 ft_s[32];    // feats = mo + h1_agg
    __shared__ float4 gs_s[32];    // feats + h2_agg
    __shared__ float  ov_s[16], le_s[16], dn_s[16];
    __shared__ int    row_s, win_s;

    if (threadIdx.x < 32) {
        int i = b * 32 + threadIdx.x;
        float4 m = ((const float4*)mo)[i];
        float4 f = g_feats4[i];
        float4 h = g_h2agg4[i];
        mo_s[threadIdx.x] = m;
        ft_s[threadIdx.x] = f;
        gs_s[threadIdx.x] = make_float4(f.x + h.x, f.y + h.y, f.z + h.z, f.w + h.w);
    }
    if (threadIdx.x == 0) {
        int r = v_idx[b];
        row_s = r;
        win_s = g_winner[r];
    }
    __syncthreads();

    // gather V_n row for (row_s, u) — stays in registers for top_states write
    const float4* vrow = (const float4*)(Vn + ((size_t)row_s * NU_ + u) * F_);
    float4 v = vrow[lane];
    float4 m = mo_s[lane];
    float4 g = gs_s[lane];

    float ov = v.x * m.x + v.y * m.y + v.z * m.z + v.w * m.w;   // overlap partial
    float le = v.x * g.x + v.y * g.y + v.z * g.z + v.w * g.w;   // loc_energy partial
    #pragma unroll
    for (int o = 16; o; o >>= 1) {
        ov += __shfl_xor_sync(0xFFFFFFFF, ov, o);
        le += __shfl_xor_sync(0xFFFFFFFF, le, o);
    }
    if (lane == 0) { ov_s[u] = ov; le_s[u] = le; }
    __syncthreads();

    // warp 0: denom = gram[b] @ overlap (16x16 matvec), p, energy
    if (u == 0) {
        float d = 0.f, l = 0.f;
        if (lane < 16) {
            const float* gr = gram + (size_t)b * (NU_ * NU_) + lane * NU_;
            #pragma unroll
            for (int vv = 0; vv < 16; vv++) d += gr[vv] * ov_s[vv];
            l = le_s[lane];
        }
        float d2 = d * d;
        float ns = l * d2;   // lanes >=16 contribute 0
        float ds = d2;
        #pragma unroll
        for (int o = 16; o; o >>= 1) {
            ns += __shfl_xor_sync(0xFFFFFFFF, ns, o);
            ds += __shfl_xor_sync(0xFFFFFFFF, ds, o);
        }
        if (lane < 16) dn_s[lane] = d;
        if (lane == 0) energy_out[b] = ns / ds;
    }
    __syncthreads();

    // winner writes top_states = tanh(V + denom[u]*feats)
    if (win_s == b) {
        float  dn = dn_s[u];
        float4 f  = ft_s[lane];
        float4 t;
        t.x = tanhf(v.x + dn * f.x);
        t.y = tanhf(v.y + dn * f.y);
        t.z = tanhf(v.z + dn * f.z);
        t.w = tanhf(v.w + dn * f.w);
        ((float4*)(vout + ((size_t)row_s * NU_ + u) * F_))[lane] = t;
    }
}

// ---------------------------------------------------------------------------
// Kernel 4: copy untouched V_n rows to output (winner rows already written)
//   1 block per row, 256 threads x 2 float4 = 2048 floats
// ---------------------------------------------------------------------------
__global__ __launch_bounds__(256)
void copy_kernel(const float* __restrict__ Vn, float* __restrict__ vout) {
    int row = blockIdx.x;
    if (g_winner[row] >= 0) return;
    const float4* src = (const float4*)(Vn   + (size_t)row * (NU_ * F_));
    float4*       dst = (float4*)      (vout + (size_t)row * (NU_ * F_));
    int t = threadIdx.x;
    dst[t]       = src[t];
    dst[t + 256] = src[t + 256];
}

// ---------------------------------------------------------------------------
extern "C" void kernel_launch(void* const* d_in, const int* in_sizes, int n_in,
                              void* d_out, int out_size) {
    const float* mo    = (const float*)d_in[0];
    const float* Vn    = (const float*)d_in[1];
    const int*   vidx  = (const int*)  d_in[2];
    const float* h1    = (const float*)d_in[3];
    const int*   h1i   = (const int*)  d_in[4];
    const float* h2    = (const float*)d_in[5];
    const int*   h2i   = (const int*)  d_in[6];
    const float* gram  = (const float*)d_in[7];

    float* energy = (float*)d_out;        // [B]
    float* vout   = energy + B_;          // [M, NU, F]

    {   // init scratch
        int n = B_ * (F_ / 4);            // 262144 >= M_? no (M=50000 < 262144) OK
        init_kernel<<<(n + 255) / 256, 256>>>((const float4*)mo);
    }
    {   // segment sums + winner
        int n = E_ * 32;                  // 2,097,152 threads (>= B_)
        scatter_kernel<<<(n + 255) / 256, 256>>>(
            (const float4*)h1, h1i, (const float4*)h2, h2i, vidx);
    }
    energy_kernel<<<B_, 512>>>(mo, Vn, vidx, gram, energy, vout);
    copy_kernel<<<M_, 256>>>(Vn, vout);
}